// round 13
// baseline (speedup 1.0000x reference)
#include <cuda_runtime.h>

#define T_STEPS 2048
#define OUT_DIM 8
#define BATCH 512

typedef unsigned long long ull;

// staging for precomputed layer-1 input projection, layout [b][t][unit*4+gate]
__device__ float g_xg[(size_t)BATCH * T_STEPS * 128];

// ---- packed fp32x2 helpers (sm_100+) ----
__device__ __forceinline__ void fma2(ull &d, ull a, ull b) {
    asm("fma.rn.f32x2 %0, %1, %2, %0;" : "+l"(d) : "l"(a), "l"(b));
}
__device__ __forceinline__ ull add2(ull a, ull b) {
    ull r; asm("add.rn.f32x2 %0, %1, %2;" : "=l"(r) : "l"(a), "l"(b)); return r;
}
__device__ __forceinline__ float red2(ull a) {
    float lo, hi;
    asm("mov.b64 {%0,%1}, %2;" : "=f"(lo), "=f"(hi) : "l"(a));
    return lo + hi;
}
__device__ __forceinline__ void lds2(ull &a, ull &b, unsigned addr) {
    asm volatile("ld.shared.v2.b64 {%0,%1}, [%2];" : "=l"(a), "=l"(b) : "r"(addr));
}

// tanh via exp; clamp high side so e stays finite (tanh(15)==1 in fp32)
__device__ __forceinline__ float tanh_(float x) {
    float e = __expf(2.0f * fminf(x, 15.0f));
    return __fdividef(e - 1.0f, e + 1.0f);
}

#define PAIR_BAR() asm volatile("bar.sync %0, 64;" :: "r"(barid) : "memory")

// =====================================================================
// prepass: g_xg[b][t][ch] = (bih0+bhh0)[r] + Wih0[r,:].x[b,t,:],
//          r = (ch&3)*32 + (ch>>2)
// grid 512 (=b), block 128: thread (j&63) owns channels 2jj,2jj+1 within
// t-half (j>>6). All 4 SMSPs used, 2 channels per thread (LDS reuse).
// =====================================================================
__global__ void __launch_bounds__(128) xg_prepass(
    const float *__restrict__ X, const float *__restrict__ Wih0,
    const float *__restrict__ bih0, const float *__restrict__ bhh0)
{
    __shared__ __align__(16) float xt[2][32 * 32];  // per half: 32 t x 32 feat
    const int j = threadIdx.x;
    const int b = blockIdx.x;
    const int half = j >> 6;
    const int jj = j & 63;
    const int ch0 = 2 * jj, ch1 = ch0 + 1;
    const int r0 = (ch0 & 3) * 32 + (ch0 >> 2);
    const int r1 = (ch1 & 3) * 32 + (ch1 >> 2);

    ull w0[16], w1[16];
    {
        const ull *p = (const ull *)(Wih0 + r0 * 32);
#pragma unroll
        for (int i = 0; i < 16; i++) w0[i] = p[i];
        p = (const ull *)(Wih0 + r1 * 32);
#pragma unroll
        for (int i = 0; i < 16; i++) w1[i] = p[i];
    }
    const float bs0 = bih0[r0] + bhh0[r0];
    const float bs1 = bih0[r1] + bhh0[r1];

    const float *xb = X + ((size_t)b * T_STEPS + half * 1024) * 32;
    float *outp = g_xg + ((size_t)b * T_STEPS + half * 1024) * 128;
    const unsigned xtb = (unsigned)__cvta_generic_to_shared(&xt[half][0]);

    for (int tt = 0; tt < 1024; tt += 32) {
        __syncthreads();
        const float4 *src = (const float4 *)(xb + tt * 32);
        float4 *dst4 = (float4 *)&xt[half][0];
#pragma unroll
        for (int k = 0; k < 4; k++) dst4[jj + k * 64] = src[jj + k * 64];
        __syncthreads();

#pragma unroll 2
        for (int t = 0; t < 32; t++) {
            ull a0 = 0ull, a1 = 0ull, c0 = 0ull, c1 = 0ull;
#pragma unroll
            for (int i = 0; i < 4; i++) {
                ull p0, p1, p2, p3;
                lds2(p0, p1, xtb + (unsigned)(t * 128 + i * 32));
                lds2(p2, p3, xtb + (unsigned)(t * 128 + i * 32 + 16));
                fma2(a0, w0[4 * i + 0], p0); fma2(a1, w0[4 * i + 1], p1);
                fma2(a0, w0[4 * i + 2], p2); fma2(a1, w0[4 * i + 3], p3);
                fma2(c0, w1[4 * i + 0], p0); fma2(c1, w1[4 * i + 1], p1);
                fma2(c0, w1[4 * i + 2], p2); fma2(c1, w1[4 * i + 3], p3);
            }
            float2 vv;
            vv.x = red2(add2(a0, a1)) + bs0;
            vv.y = red2(add2(c0, c1)) + bs1;
            *(float2 *)(outp + (size_t)(tt + t) * 128 + ch0) = vv;
        }
    }
}

// =====================================================================
// recurrent kernel: 256 threads = 4 pairs; pair = 64 thr = 1 batch element.
// Lane pair (2u, 2u+1) owns hidden unit u for BOTH layers:
//   sub=0 lane: gate rows {i,f};  sub=1 lane: gate rows {g,o}.
// warp0 = units 0-15, warp1 = units 16-31.
// Gate exchange via shfl_xor(1); 2 named barriers/step; h double-buffered.
// All activations through one tanh chain: sigm(x) = 0.5*tanh(x/2)+0.5.
// =====================================================================
__global__ void __launch_bounds__(256, 1) lstm_rec(
    const float *__restrict__ Whh0,
    const float *__restrict__ Wih1, const float *__restrict__ Whh1,
    const float *__restrict__ bih1, const float *__restrict__ bhh1,
    const float *__restrict__ Wfc, const float *__restrict__ bfc,
    float *__restrict__ out)
{
    __shared__ __align__(16) float h1s[4][2][32];
    __shared__ __align__(16) float h2s[4][2][32];

    const int tid = threadIdx.x;
    const int pair = tid >> 6;        // 0..3
    const int lt = tid & 63;
    const int b = blockIdx.x * 4 + pair;
    const int barid = 1 + pair;       // named barrier per pair
    const int wrp = lt >> 5;          // warp in pair
    const int l = lt & 31;            // lane
    const int u = wrp * 16 + (l >> 1);// owned hidden unit
    const int sub = l & 1;            // 0: gates i,f   1: gates g,o
    const int r0 = (sub * 2) * 32 + u;
    const int r1 = (sub * 2 + 1) * 32 + u;

    // activation constants: act = m*tanh(s*gate) + a
    //   sub=0: both gates sigmoid;  sub=1: gate0=tanh(g), gate1=sigmoid(o)
    const float s0 = sub ? 1.0f : 0.5f;
    const float m0 = sub ? 1.0f : 0.5f;
    const float a0c = sub ? 0.0f : 0.5f;

    // ---- register-resident weights: 6 rows = 96 ull = 192 regs ----
    ull wh00[16], wh01[16], wi10[16], wi11[16], wh10[16], wh11[16];
    {
        const ull *p;
        p = (const ull *)(Whh0 + r0 * 32);
#pragma unroll
        for (int i = 0; i < 16; i++) wh00[i] = p[i];
        p = (const ull *)(Whh0 + r1 * 32);
#pragma unroll
        for (int i = 0; i < 16; i++) wh01[i] = p[i];
        p = (const ull *)(Wih1 + r0 * 32);
#pragma unroll
        for (int i = 0; i < 16; i++) wi10[i] = p[i];
        p = (const ull *)(Wih1 + r1 * 32);
#pragma unroll
        for (int i = 0; i < 16; i++) wi11[i] = p[i];
        p = (const ull *)(Whh1 + r0 * 32);
#pragma unroll
        for (int i = 0; i < 16; i++) wh10[i] = p[i];
        p = (const ull *)(Whh1 + r1 * 32);
#pragma unroll
        for (int i = 0; i < 16; i++) wh11[i] = p[i];
    }
    const float b2r0 = bih1[r0] + bhh1[r0];
    const float b2r1 = bih1[r1] + bhh1[r1];

    // xg stream: float2 of channels (4u+2sub, 4u+2sub+1) = rows (r0, r1)
    const float2 *xgp = (const float2 *)(g_xg + (size_t)b * T_STEPS * 128)
                        + 2 * (u & 15) + 32 * wrp + sub;
    float2 cur = __ldg(xgp);
    float2 nxt = __ldg(xgp + 64);

    if (lt < 32) { h1s[pair][1][lt] = 0.0f; h2s[pair][1][lt] = 0.0f; }
    float c1 = 0.0f, c2 = 0.0f;

    const unsigned h1b = (unsigned)__cvta_generic_to_shared(&h1s[pair][0][0]);
    const unsigned h2b = (unsigned)__cvta_generic_to_shared(&h2s[pair][0][0]);
    __syncthreads();

#pragma unroll 1
    for (int t = 0; t < T_STEPS; t++) {
        // prefetch xg(t+2)
        float2 pre;
        {
            int tf = t + 2; if (tf > T_STEPS - 1) tf = T_STEPS - 1;
            pre = __ldg(xgp + (size_t)tf * 64);
        }
        const unsigned bNew = (unsigned)((t & 1) << 7);      // byte offset
        const unsigned bOld = (unsigned)(((t + 1) & 1) << 7);

        // ===== phase 1: layer-1 rows r0,r1 over h1(t-1); update c1,h1(u) =====
        ull A0 = 0ull, A1 = 0ull, D0 = 0ull, D1 = 0ull;
#pragma unroll
        for (int i = 0; i < 4; i++) {
            ull p0, p1, p2, p3;
            lds2(p0, p1, h1b + bOld + (unsigned)(i * 32));
            lds2(p2, p3, h1b + bOld + (unsigned)(i * 32 + 16));
            fma2(A0, wh00[4 * i + 0], p0); fma2(A1, wh00[4 * i + 1], p1);
            fma2(A0, wh00[4 * i + 2], p2); fma2(A1, wh00[4 * i + 3], p3);
            fma2(D0, wh01[4 * i + 0], p0); fma2(D1, wh01[4 * i + 1], p1);
            fma2(D0, wh01[4 * i + 2], p2); fma2(D1, wh01[4 * i + 3], p3);
        }
        float g0 = red2(add2(A0, A1)) + cur.x;
        float g1 = red2(add2(D0, D1)) + cur.y;
        float act0 = fmaf(m0, tanh_(s0 * g0), a0c);     // i  (or g)
        float act1 = fmaf(0.5f, tanh_(0.5f * g1), 0.5f);// f  (or o)
        float o0 = __shfl_xor_sync(0xffffffffu, act0, 1);
        float o1 = __shfl_xor_sync(0xffffffffu, act1, 1);
        {
            float iv = sub ? o0 : act0;
            float fv = sub ? o1 : act1;
            float gv = sub ? act0 : o0;
            float ov = sub ? act1 : o1;
            c1 = fmaf(fv, c1, iv * gv);
            float h = ov * tanh_(c1);
            if (!sub) h1s[pair][t & 1][u] = h;
        }
        PAIR_BAR();                                      // publish h1(t)

        // ===== phase 2: layer-2 rows r0,r1 over [h1(t) | h2(t-1)]; c2,h2 =====
        A0 = 0ull; A1 = 0ull; D0 = 0ull; D1 = 0ull;
#pragma unroll
        for (int i = 0; i < 4; i++) {
            ull p0, p1, p2, p3;
            lds2(p0, p1, h1b + bNew + (unsigned)(i * 32));
            lds2(p2, p3, h1b + bNew + (unsigned)(i * 32 + 16));
            fma2(A0, wi10[4 * i + 0], p0); fma2(A1, wi10[4 * i + 1], p1);
            fma2(A0, wi10[4 * i + 2], p2); fma2(A1, wi10[4 * i + 3], p3);
            fma2(D0, wi11[4 * i + 0], p0); fma2(D1, wi11[4 * i + 1], p1);
            fma2(D0, wi11[4 * i + 2], p2); fma2(D1, wi11[4 * i + 3], p3);
        }
#pragma unroll
        for (int i = 0; i < 4; i++) {
            ull p0, p1, p2, p3;
            lds2(p0, p1, h2b + bOld + (unsigned)(i * 32));
            lds2(p2, p3, h2b + bOld + (unsigned)(i * 32 + 16));
            fma2(A0, wh10[4 * i + 0], p0); fma2(A1, wh10[4 * i + 1], p1);
            fma2(A0, wh10[4 * i + 2], p2); fma2(A1, wh10[4 * i + 3], p3);
            fma2(D0, wh11[4 * i + 0], p0); fma2(D1, wh11[4 * i + 1], p1);
            fma2(D0, wh11[4 * i + 2], p2); fma2(D1, wh11[4 * i + 3], p3);
        }
        g0 = red2(add2(A0, A1)) + b2r0;
        g1 = red2(add2(D0, D1)) + b2r1;
        act0 = fmaf(m0, tanh_(s0 * g0), a0c);
        act1 = fmaf(0.5f, tanh_(0.5f * g1), 0.5f);
        o0 = __shfl_xor_sync(0xffffffffu, act0, 1);
        o1 = __shfl_xor_sync(0xffffffffu, act1, 1);
        {
            float iv = sub ? o0 : act0;
            float fv = sub ? o1 : act1;
            float gv = sub ? act0 : o0;
            float ov = sub ? act1 : o1;
            c2 = fmaf(fv, c2, iv * gv);
            float h = ov * tanh_(c2);
            if (!sub) h2s[pair][t & 1][u] = h;
        }
        PAIR_BAR();                                      // publish h2(t)

        cur = nxt; nxt = pre;
    }
    __syncthreads();

    // ===== FC head on h2(T-1) (buffer 1) =====
    if (lt < OUT_DIM) {
        float s = bfc[lt];
        const float *wf = Wfc + lt * 32;
#pragma unroll
        for (int k = 0; k < 32; k++) s = fmaf(wf[k], h2s[pair][1][k], s);
        out[b * OUT_DIM + lt] = s;
    }
}

extern "C" void kernel_launch(void* const* d_in, const int* in_sizes, int n_in,
                              void* d_out, int out_size) {
    (void)in_sizes; (void)n_in; (void)out_size;
    const float *X    = (const float *)d_in[0];
    const float *Wih0 = (const float *)d_in[1];
    const float *Whh0 = (const float *)d_in[2];
    const float *bih0 = (const float *)d_in[3];
    const float *bhh0 = (const float *)d_in[4];
    const float *Wih1 = (const float *)d_in[5];
    const float *Whh1 = (const float *)d_in[6];
    const float *bih1 = (const float *)d_in[7];
    const float *bhh1 = (const float *)d_in[8];
    const float *Wfc  = (const float *)d_in[9];
    const float *bfc  = (const float *)d_in[10];

    xg_prepass<<<BATCH, 128>>>(X, Wih0, bih0, bhh0);
    lstm_rec<<<BATCH / 4, 256>>>(Whh0, Wih1, Whh1, bih1, bhh1, Wfc, bfc,
                                 (float *)d_out);
}